// round 16
// baseline (speedup 1.0000x reference)
#include <cuda_runtime.h>
#include <cuda_bf16.h>
#include <cstdint>

// ---------------------------------------------------------------------------
// Problem: B=4, T=2048, C=1024, H=16, D=64.  out = attn(xWq, xWk, xWv) Wo
// All GEMMs + attention on HMMA (mma.sync bf16, 3-term hi/lo split).
// R16: GEMM inner loop restructured into 3 passes so dependent HMMAs on the
//      same accumulator are >=12 issues apart (was 0 -> serialized on the
//      tensor-core accumulation latency). Numerics bit-identical.
//      Attention/splits/launch = R14 (proven).
// ---------------------------------------------------------------------------
#define BB   4
#define TT   2048
#define CC   1024
#define HH   16
#define DD   64
#define MROWS (BB*TT)          // 8192
#define KDIM 1024
#define NDIM 1024
#define KOFF ((size_t)BB*HH*TT*DD)     // per-matrix q/k/v span

// ---- scratch ---------------------------------------------------------------
__device__ __nv_bfloat16 g_qkvhi[3*BB*HH*TT*DD], g_qkvlo[3*BB*HH*TT*DD];
__device__ __nv_bfloat16 g_xhi[MROWS*KDIM], g_xlo[MROWS*KDIM];
__device__ __nv_bfloat16 g_yhi[MROWS*KDIM], g_ylo[MROWS*KDIM];
__device__ __nv_bfloat16 g_wallhi[3*NDIM*KDIM], g_walllo[3*NDIM*KDIM];
__device__ __nv_bfloat16 g_wohi[NDIM*KDIM], g_wolo[NDIM*KDIM];

__device__ __forceinline__ uint32_t smem_u32(const void* p) {
    uint32_t a;
    asm("{ .reg .u64 t; cvta.to.shared.u64 t, %1; cvt.u32.u64 %0, t; }"
        : "=r"(a) : "l"(p));
    return a;
}
__device__ __forceinline__ void ldsm4(uint32_t& r0, uint32_t& r1,
                                      uint32_t& r2, uint32_t& r3, uint32_t addr) {
    asm volatile("ldmatrix.sync.aligned.m8n8.x4.shared.b16 {%0,%1,%2,%3}, [%4];"
                 : "=r"(r0), "=r"(r1), "=r"(r2), "=r"(r3) : "r"(addr));
}
__device__ __forceinline__ void ldsm4t(uint32_t& r0, uint32_t& r1,
                                       uint32_t& r2, uint32_t& r3, uint32_t addr) {
    asm volatile("ldmatrix.sync.aligned.m8n8.x4.trans.shared.b16 {%0,%1,%2,%3}, [%4];"
                 : "=r"(r0), "=r"(r1), "=r"(r2), "=r"(r3) : "r"(addr));
}
#define MMA_BF16(d, a, b0, b1)                                              \
    asm volatile("mma.sync.aligned.m16n8k16.row.col.f32.bf16.bf16.f32 "     \
                 "{%0,%1,%2,%3}, {%4,%5,%6,%7}, {%8,%9}, {%0,%1,%2,%3};"    \
                 : "+f"((d)[0]), "+f"((d)[1]), "+f"((d)[2]), "+f"((d)[3])   \
                 : "r"((a)[0]), "r"((a)[1]), "r"((a)[2]), "r"((a)[3]),      \
                   "r"(b0), "r"(b1))
__device__ __forceinline__ void cpa16(uint32_t dst, const void* src) {
    asm volatile("cp.async.cg.shared.global [%0], [%1], 16;"
                 :: "r"(dst), "l"(src));
}
#define CP_COMMIT() asm volatile("cp.async.commit_group;")
#define CP_WAIT(n)  asm volatile("cp.async.wait_group %0;" :: "n"(n))
__device__ __forceinline__ float ex2f(float x) {
    float y; asm("ex2.approx.ftz.f32 %0, %1;" : "=f"(y) : "f"(x)); return y;
}
// rn split (one-time input splits)
__device__ __forceinline__ void split2(float a, float b, uint32_t& hi, uint32_t& lo) {
    __nv_bfloat16 ha = __float2bfloat16_rn(a), hb = __float2bfloat16_rn(b);
    __nv_bfloat16 la = __float2bfloat16_rn(a - __bfloat162float(ha));
    __nv_bfloat16 lb = __float2bfloat16_rn(b - __bfloat162float(hb));
    __nv_bfloat162 vh = __halves2bfloat162(ha, hb), vl = __halves2bfloat162(la, lb);
    hi = *(uint32_t*)&vh; lo = *(uint32_t*)&vl;
}
// truncation split: hi = {b.hi16, a.hi16} via PRMT; lo = rn(residual)
__device__ __forceinline__ void split2t(float a, float b, uint32_t& hi, uint32_t& lo) {
    const uint32_t ua = __float_as_uint(a), ub = __float_as_uint(b);
    hi = __byte_perm(ua, ub, 0x7632);
    const float ra = a - __uint_as_float(ua & 0xFFFF0000u);
    const float rb = b - __uint_as_float(ub & 0xFFFF0000u);
    asm("cvt.rn.bf16x2.f32 %0, %1, %2;" : "=r"(lo) : "f"(rb), "f"(ra));
}

// ---------------------------------------------------------------------------
// split kernels
// ---------------------------------------------------------------------------
__global__ void split_kernel(const float* __restrict__ src,
                             __nv_bfloat16* __restrict__ hi,
                             __nv_bfloat16* __restrict__ lo, int n)
{
    int i = (blockIdx.x * blockDim.x + threadIdx.x) * 4;
    if (i >= n) return;
    float4 v = *(const float4*)(src + i);
    uint32_t h0, l0, h1, l1;
    split2(v.x, v.y, h0, l0);
    split2(v.z, v.w, h1, l1);
    *(uint32_t*)(hi + i)     = h0; *(uint32_t*)(hi + i + 2) = h1;
    *(uint32_t*)(lo + i)     = l0; *(uint32_t*)(lo + i + 2) = l1;
}

__global__ void split_w3(const float* __restrict__ w0, const float* __restrict__ w1,
                         const float* __restrict__ w2,
                         __nv_bfloat16* __restrict__ hi, __nv_bfloat16* __restrict__ lo)
{
    const int mat = blockIdx.y;
    const float* src = (mat == 0) ? w0 : (mat == 1) ? w1 : w2;
    const size_t base = (size_t)mat * NDIM * KDIM;
    int i = (blockIdx.x * blockDim.x + threadIdx.x) * 4;
    float4 v = *(const float4*)(src + i);
    uint32_t h0, l0, h1, l1;
    split2(v.x, v.y, h0, l0);
    split2(v.z, v.w, h1, l1);
    *(uint32_t*)(hi + base + i)     = h0; *(uint32_t*)(hi + base + i + 2) = h1;
    *(uint32_t*)(lo + base + i)     = l0; *(uint32_t*)(lo + base + i + 2) = l1;
}

__global__ void split_transpose(const float* __restrict__ W,
                                __nv_bfloat16* __restrict__ hi,
                                __nv_bfloat16* __restrict__ lo)
{
    __shared__ float tile[32][33];
    const int n0 = blockIdx.x * 32, k0 = blockIdx.y * 32;
    const int tx = threadIdx.x, ty = threadIdx.y;
    tile[ty][tx] = W[(k0 + ty) * NDIM + n0 + tx];
    __syncthreads();
    float v = tile[tx][ty];
    __nv_bfloat16 h = __float2bfloat16_rn(v);
    __nv_bfloat16 l = __float2bfloat16_rn(v - __bfloat162float(h));
    const int o = (n0 + ty) * KDIM + k0 + tx;
    hi[o] = h;
    lo[o] = l;
}

// ---------------------------------------------------------------------------
// HMMA GEMM, 3-stage swizzled cp.async pipeline, 2 CTAs/SM, 256 threads,
// 8 warps of 32x64 tiles. Inner loop in 3 passes for dependency spacing.
//   QKV=true  (PERSIST=false): grid (64, 24); split-bf16 scatter epilogue.
//   QKV=false (PERSIST=true) : grid 296, loops 512 tiles; fp32 epilogue.
// ---------------------------------------------------------------------------
#define TILE_B   (128 * 64)               // 8192 bytes per tile
#define STAGE_B  (4 * TILE_B)             // 32768
#define NSTG     3
#define OPROJ_GRID 296

template <bool QKV, bool PERSIST>
__global__ __launch_bounds__(256, 2)
void hmma_gemm(const __nv_bfloat16* __restrict__ Ahi, const __nv_bfloat16* __restrict__ Alo,
               const __nv_bfloat16* __restrict__ BhiAll, const __nv_bfloat16* __restrict__ BloAll,
               float* __restrict__ C,
               __nv_bfloat16* __restrict__ Chi, __nv_bfloat16* __restrict__ Clo)
{
    extern __shared__ __align__(128) char sm[];
    const int tid  = threadIdx.x;
    const int wid  = tid >> 5;
    const int lane = tid & 31;

    const int wm0 = (wid & 3) * 32;
    const int wn0 = (wid >> 2) * 64;

    const int r0c = tid >> 2, c0c = tid & 3;
    const uint32_t smb = smem_u32(sm);
    const uint32_t s0 = r0c * 64 + ((c0c ^ ((r0c >> 1) & 3)) << 4);
    const uint32_t s1 = s0 + 64 * 64;

    // ldsm addressing (loop-invariant)
    const uint32_t aRow = wm0 + (lane & 15);
    const uint32_t aChunkBase = (lane >> 4);
    const uint32_t aXor = (aRow >> 1) & 3;
    const uint32_t g = lane >> 3;
    const uint32_t bRow = wn0 + (lane & 7) + ((g >> 1) << 3);
    const uint32_t bChunkBase = (g & 1);
    const uint32_t bXor = (bRow >> 1) & 3;

    const int NT   = PERSIST ? (64 * 8) : 1;
    const int step = PERSIST ? OPROJ_GRID : 1;

    for (int t = blockIdx.x; t < NT || !PERSIST; t += step) {
        int m0, n0, mat;
        if (PERSIST) {
            m0  = (t & 63) * 128;
            n0  = (t >> 6) * 128;
            mat = 0;
        } else {
            m0  = blockIdx.x * 128;
            mat = QKV ? (blockIdx.y >> 3) : 0;
            n0  = (QKV ? (blockIdx.y & 7) : blockIdx.y) * 128;
        }

        const __nv_bfloat16* Bhi = BhiAll + (size_t)mat * NDIM * KDIM;
        const __nv_bfloat16* Blo = BloAll + (size_t)mat * NDIM * KDIM;

        const size_t ga0 = (size_t)(m0 + r0c) * KDIM + c0c * 8;
        const size_t ga1 = (size_t)(m0 + r0c + 64) * KDIM + c0c * 8;
        const size_t gb0 = (size_t)(n0 + r0c) * KDIM + c0c * 8;
        const size_t gb1 = (size_t)(n0 + r0c + 64) * KDIM + c0c * 8;

        auto issue = [&](int st, int kt) {
            const int kc = kt * 32;
            const uint32_t bb = smb + st * STAGE_B;
            cpa16(bb + 0 * TILE_B + s0, Ahi + ga0 + kc);
            cpa16(bb + 0 * TILE_B + s1, Ahi + ga1 + kc);
            cpa16(bb + 1 * TILE_B + s0, Alo + ga0 + kc);
            cpa16(bb + 1 * TILE_B + s1, Alo + ga1 + kc);
            cpa16(bb + 2 * TILE_B + s0, Bhi + gb0 + kc);
            cpa16(bb + 2 * TILE_B + s1, Bhi + gb1 + kc);
            cpa16(bb + 3 * TILE_B + s0, Blo + gb0 + kc);
            cpa16(bb + 3 * TILE_B + s1, Blo + gb1 + kc);
            CP_COMMIT();
        };

        if (PERSIST) __syncthreads();   // protect smem vs previous tile readers
        issue(0, 0);
        issue(1, 1);

        float acc[2][8][4];
#pragma unroll
        for (int i = 0; i < 2; i++)
#pragma unroll
            for (int j = 0; j < 8; j++)
#pragma unroll
                for (int q = 0; q < 4; q++) acc[i][j][q] = 0.f;

        for (int kt = 0; kt < 32; kt++) {
            const int st = kt % NSTG;
            if (kt < 31) { CP_WAIT(1); } else { CP_WAIT(0); }
            __syncthreads();
            if (kt < 30) issue((kt + 2) % NSTG, kt + 2);

            const uint32_t base = smb + st * STAGE_B;
#pragma unroll
            for (int ksub = 0; ksub < 2; ksub++) {
                const uint32_t cA = (ksub * 2 + aChunkBase) ^ aXor;
                const uint32_t cB = (ksub * 2 + bChunkBase) ^ bXor;

                // ---- load A frags (hi+lo) and ALL B-hi frags --------------
                uint32_t ahi[2][4], alo[2][4];
#pragma unroll
                for (int mi = 0; mi < 2; mi++) {
                    const uint32_t off = (aRow + mi * 16) * 64 + (cA << 4);
                    ldsm4(ahi[mi][0], ahi[mi][1], ahi[mi][2], ahi[mi][3],
                          base + 0 * TILE_B + off);
                    ldsm4(alo[mi][0], alo[mi][1], alo[mi][2], alo[mi][3],
                          base + 1 * TILE_B + off);
                }
                uint32_t bh[4][4];
#pragma unroll
                for (int pj = 0; pj < 4; pj++) {
                    const uint32_t off = (bRow + pj * 16) * 64 + (cB << 4);
                    ldsm4(bh[pj][0], bh[pj][1], bh[pj][2], bh[pj][3],
                          base + 2 * TILE_B + off);
                }

                // ---- pass 1: ahi * bhi (16 MMAs, unique targets) ----------
#pragma unroll
                for (int pj = 0; pj < 4; pj++)
#pragma unroll
                    for (int mi = 0; mi < 2; mi++) {
                        MMA_BF16(acc[mi][2*pj],   ahi[mi], bh[pj][0], bh[pj][1]);
                        MMA_BF16(acc[mi][2*pj+1], ahi[mi], bh[pj][2], bh[pj][3]);
                    }

                // ---- pass 2: ahi * blo (blo streamed per pj) --------------
#pragma unroll
                for (int pj = 0; pj < 4; pj++) {
                    const uint32_t off = (bRow + pj * 16) * 64 + (cB << 4);
                    uint32_t bl[4];
                    ldsm4(bl[0], bl[1], bl[2], bl[3], base + 3 * TILE_B + off);
#pragma unroll
                    for (int mi = 0; mi < 2; mi++) {
                        MMA_BF16(acc[mi][2*pj],   ahi[mi], bl[0], bl[1]);
                        MMA_BF16(acc[mi][2*pj+1], ahi[mi], bl[2], bl[3]);
                    }
                }

                // ---- pass 3: alo * bhi (16 MMAs) --------------------------
#pragma unroll
                for (int pj = 0; pj < 4; pj++)
#pragma unroll
                    for (int mi = 0; mi < 2; mi++) {
                        MMA_BF16(acc[mi][2*pj],   alo[mi], bh[pj][0], bh[pj][1]);
                        MMA_BF16(acc[mi][2*pj+1], alo[mi], bh[pj][2], bh[pj][3]);
                    }
            }
        }

        // ---- epilogue -----------------------------------------------------
        const float preScale = (QKV && mat == 0) ? (0.125f * 1.44269504088896341f) : 1.0f;
#pragma unroll
        for (int mi = 0; mi < 2; mi++) {
#pragma unroll
            for (int nt = 0; nt < 8; nt++) {
                const int mrow0 = m0 + wm0 + mi * 16 + (lane >> 2);
                const int ncol  = n0 + wn0 + nt * 8 + (lane & 3) * 2;
                if (QKV) {
                    const int h = ncol >> 6, d = ncol & 63;
#pragma unroll
                    for (int half = 0; half < 2; half++) {
                        const int m = mrow0 + half * 8;
                        const int b = m >> 11, tt2 = m & 2047;
                        const size_t off = (size_t)mat * KOFF
                                         + (((size_t)(b * HH + h) * TT + tt2) * DD + d);
                        uint32_t hh, ll;
                        split2t(acc[mi][nt][half * 2] * preScale,
                                acc[mi][nt][half * 2 + 1] * preScale, hh, ll);
                        *(uint32_t*)(Chi + off) = hh;
                        *(uint32_t*)(Clo + off) = ll;
                    }
                } else {
#pragma unroll
                    for (int half = 0; half < 2; half++) {
                        float* o = C + (size_t)(mrow0 + half * 8) * NDIM + ncol;
                        *(float2*)o = make_float2(acc[mi][nt][half * 2],
                                                  acc[mi][nt][half * 2 + 1]);
                    }
                }
            }
        }
        if (!PERSIST) break;
    }
}

// ---------------------------------------------------------------------------
// HMMA flash attention (R11/R14-proven). CTA = 128 q-rows, 8 warps, block 256.
// Q staged through stage 0 then recycled; 3-stage K/V cp.async ring.
// grid = (16 qtiles [reversed], 64 bh). 2 CTAs/SM.
// ---------------------------------------------------------------------------
#define ASTRB    144
#define ATILE_B  (64 * ASTRB)              // 9216
#define ASTAGE_B (4 * ATILE_B)             // 36864
#define ASMEM_TOTAL (3 * ASTAGE_B)         // 110592

__global__ __launch_bounds__(256, 2)
void attn_mma(const __nv_bfloat16* __restrict__ QKVhi,
              const __nv_bfloat16* __restrict__ QKVlo,
              __nv_bfloat16* __restrict__ Yhi, __nv_bfloat16* __restrict__ Ylo)
{
    extern __shared__ __align__(128) char smA[];
    const int tid  = threadIdx.x;
    const int wid  = tid >> 5;
    const int lane = tid & 31;
    const int qt   = (int)(gridDim.x - 1) - (int)blockIdx.x;
    const int bh   = blockIdx.y;
    const int b    = bh >> 4;
    const int h    = bh & 15;
    const int q0   = qt * 128;

    const size_t bho = (size_t)bh * TT * DD;
    const __nv_bfloat16* qh = QKVhi + bho;
    const __nv_bfloat16* ql = QKVlo + bho;
    const __nv_bfloat16* kh = QKVhi + KOFF + bho;
    const __nv_bfloat16* kl = QKVlo + KOFF + bho;
    const __nv_bfloat16* vh = QKVhi + 2 * KOFF + bho;
    const __nv_bfloat16* vl = QKVlo + 2 * KOFF + bho;

    const uint32_t smb = smem_u32(smA);

    auto issue_stage = [&](int buf, int ktile) {
        const uint32_t sb = smb + buf * ASTAGE_B;
        const int k0 = ktile * 64;
#pragma unroll
        for (int i = 0; i < 2; i++) {
            const int c = tid + i * 256;
            const int r = c >> 3, col = c & 7;
            const uint32_t doff = r * ASTRB + col * 16;
            const size_t goff = (size_t)(k0 + r) * DD + col * 8;
            cpa16(sb + 0 * ATILE_B + doff, kh + goff);
            cpa16(sb + 1 * ATILE_B + doff, kl + goff);
            cpa16(sb + 2 * ATILE_B + doff, vh + goff);
            cpa16(sb + 3 * ATILE_B + doff, vl + goff);
        }
        CP_COMMIT();
    };

    // ---- stage Q through stage 0: hi -> tiles 0,1 ; lo -> tiles 2,3 -------
    {
#pragma unroll
        for (int i = 0; i < 4; i++) {
            const int c = tid + i * 256;
            const int r = c >> 3, col = c & 7;
            const uint32_t doff = (r >> 6) * ATILE_B + (r & 63) * ASTRB + col * 16;
            const size_t goff = (size_t)(q0 + r) * DD + col * 8;
            cpa16(smb + doff, qh + goff);
            cpa16(smb + 2 * ATILE_B + doff, ql + goff);
        }
        CP_COMMIT();
    }
    CP_WAIT(0);
    __syncthreads();

    // ---- persistent Q fragments -------------------------------------------
    const int l7  = lane & 7;
    const int l8  = (lane >> 3) & 1;
    const int l16 = lane >> 4;
    uint32_t qfh[4][4], qfl[4][4];
    {
        const uint32_t qrow = wid * 16 + l7 + l8 * 8;
        const uint32_t qbase = (qrow >> 6) * ATILE_B + (qrow & 63) * ASTRB;
#pragma unroll
        for (int kc = 0; kc < 4; kc++) {
            const uint32_t off = qbase + kc * 32 + l16 * 16;
            ldsm4(qfh[kc][0], qfh[kc][1], qfh[kc][2], qfh[kc][3], smb + off);
            ldsm4(qfl[kc][0], qfl[kc][1], qfl[kc][2], qfl[kc][3],
                  smb + 2 * ATILE_B + off);
        }
    }
    __syncthreads();          // Q reads done; ring stage 0 reusable

    issue_stage(0, 0);
    issue_stage(1, 1);

    float accO[8][4];
    float mrow[2], lrow[2];
#pragma unroll
    for (int nt = 0; nt < 8; nt++)
#pragma unroll
        for (int q = 0; q < 4; q++) accO[nt][q] = 0.f;
    mrow[0] = mrow[1] = -1e30f;
    lrow[0] = lrow[1] = 0.f;

    const int rowg0 = q0 + wid * 16 + (lane >> 2);
    const int colg0 = (lane & 3) * 2;
    const int nk = 2 * (qt + 1);

    for (int kt = 0; kt < nk; kt++) {
        const int st = kt % 3;
        if (kt < nk - 1) { CP_WAIT(1); } else { CP_WAIT(0); }
        __syncthreads();
        if (kt + 2 < nk) issue_stage((kt + 2) % 3, kt + 2);

        const uint32_t base = smb + st * ASTAGE_B;

        // ---- S = Q K^T (3-term) -------------------------------------------
        float S[8][4];
#pragma unroll
        for (int nt = 0; nt < 8; nt++)
#pragma unroll
            for (int q = 0; q < 4; q++) S[nt][q] = 0.f;

        const uint32_t krow = l7 + l8 * 8;
#pragma unroll
        for (int kc = 0; kc < 4; kc++) {
#pragma unroll
            for (int p = 0; p < 4; p++) {
                const uint32_t off = (p * 16 + krow) * ASTRB + kc * 32 + l16 * 16;
                uint32_t b4h[4], b4l[4];
                ldsm4(b4h[0], b4h[1], b4h[2], b4h[3], base + 0 * ATILE_B + off);
                ldsm4(b4l[0], b4l[1], b4l[2], b4l[3], base + 1 * ATILE_B + off);
                MMA_BF16(S[2*p],   qfh[kc], b4h[0], b4h[2]);
                MMA_BF16(S[2*p],   qfh[kc], b4l[0], b4l[2]);
                MMA_BF16(S[2*p],   qfl[kc], b4h[0], b4h[2]);
                MMA_BF16(S[2*p+1], qfh[kc], b4h[1], b4h[3]);
                MMA_BF16(S[2*p+1], qfh[kc], b4l[1], b4l[3]);
                MMA_BF16(S[2*p+1], qfl[kc], b4h[1], b4h[3]);
            }
        }

        // ---- causal mask (only tiles crossing this warp's rows) -----------
        const int k0g = kt * 64;
        if (k0g + 63 > q0 + wid * 16) {
#pragma unroll
            for (int nt = 0; nt < 8; nt++) {
                const int cg = k0g + nt * 8 + colg0;
#pragma unroll
                for (int i = 0; i < 2; i++) {
                    const int rg = rowg0 + i * 8;
                    if (cg     > rg) S[nt][2*i]     = -1e30f;
                    if (cg + 1 > rg) S[nt][2*i + 1] = -1e30f;
                }
            }
        }

        // ---- online softmax (log2 units; scale folded into Q) -------------
#pragma unroll
        for (int i = 0; i < 2; i++) {
            float mx = -1e30f;
#pragma unroll
            for (int nt = 0; nt < 8; nt++)
                mx = fmaxf(mx, fmaxf(S[nt][2*i], S[nt][2*i+1]));
            mx = fmaxf(mx, __shfl_xor_sync(0xffffffffu, mx, 1));
            mx = fmaxf(mx, __shfl_xor_sync(0xffffffffu, mx, 2));
            const float mn = fmaxf(mrow[i], mx);
            const float fac = ex2f(mrow[i] - mn);
            float rs = 0.f;
#pragma unroll
            for (int nt = 0; nt < 8; nt++) {
                float p0 = ex2f(S[nt][2*i]   - mn);
                float p1 = ex2f(S[nt][2*i+1] - mn);
                S[nt][2*i] = p0; S[nt][2*i+1] = p1;
                rs += p0 + p1;
            }
            rs += __shfl_xor_sync(0xffffffffu, rs, 1);
            rs += __shfl_xor_sync(0xffffffffu, rs, 2);
            lrow[i] = lrow[i] * fac + rs;
            mrow[i] = mn;
#pragma unroll
            for (int nt = 0; nt < 8; nt++) {
                accO[nt][2*i]   *= fac;
                accO[nt][2*i+1] *= fac;
            }
        }

        // ---- O += P V (3-term), P packed in-register (PRMT split) ---------
#pragma unroll
        for (int kc = 0; kc < 4; kc++) {
            uint32_t pah[4], pal[4];
            split2t(S[2*kc][0],   S[2*kc][1],   pah[0], pal[0]);
            split2t(S[2*kc][2],   S[2*kc][3],   pah[1], pal[1]);
            split2t(S[2*kc+1][0], S[2*kc+1][1], pah[2], pal[2]);
            split2t(S[2*kc+1][2], S[2*kc+1][3], pah[3], pal[3]);
#pragma unroll
            for (int p = 0; p < 4; p++) {
                const uint32_t off = (kc * 16 + krow) * ASTRB + p * 32 + l16 * 16;
                uint32_t v4h[4], v4l[4];
                ldsm4t(v4h[0], v4h[1], v4h[2], v4h[3], base + 2 * ATILE_B + off);
                ldsm4t(v4l[0], v4l[1], v4l[2], v4l[3], base + 3 * ATILE_B + off);
                MMA_BF16(accO[2*p],   pah, v4h[0], v4h[1]);
                MMA_BF16(accO[2*p],   pah, v4l[0], v4l[1]);
                MMA_BF16(accO[2*p],   pal, v4h[0], v4h[1]);
                MMA_BF16(accO[2*p+1], pah, v4h[2], v4h[3]);
                MMA_BF16(accO[2*p+1], pah, v4l[2], v4l[3]);
                MMA_BF16(accO[2*p+1], pal, v4h[2], v4h[3]);
            }
        }
    }

    // ---- epilogue: y[b,t,h*64+d] split bf16 -------------------------------
    const float inv0 = 1.0f / lrow[0];
    const float inv1 = 1.0f / lrow[1];
#pragma unroll
    for (int i = 0; i < 2; i++) {
        const float inv = i ? inv1 : inv0;
#pragma unroll
        for (int nt = 0; nt < 8; nt++) {
            const int d = nt * 8 + colg0;
            const size_t off = ((size_t)(b * TT + (rowg0 + i * 8))) * CC + h * DD + d;
            uint32_t hh, ll;
            split2t(accO[nt][2*i] * inv, accO[nt][2*i+1] * inv, hh, ll);
            *(uint32_t*)(Yhi + off) = hh;
            *(uint32_t*)(Ylo + off) = ll;
        }
    }
}

// ---------------------------------------------------------------------------
// launch
// ---------------------------------------------------------------------------
extern "C" void kernel_launch(void* const* d_in, const int* in_sizes, int n_in,
                              void* d_out, int out_size)
{
    const float* x_q = (const float*)d_in[0];
    const float* w_q = (const float*)d_in[1];
    const float* w_k = (const float*)d_in[2];
    const float* w_v = (const float*)d_in[3];
    const float* w_o = (const float*)d_in[4];
    float* out = (float*)d_out;

    __nv_bfloat16 *qkvhi, *qkvlo, *xhi, *xlo, *yhi, *ylo;
    __nv_bfloat16 *wallhi, *walllo, *wohi, *wolo;
    cudaGetSymbolAddress((void**)&qkvhi, g_qkvhi);
    cudaGetSymbolAddress((void**)&qkvlo, g_qkvlo);
    cudaGetSymbolAddress((void**)&xhi, g_xhi);   cudaGetSymbolAddress((void**)&xlo, g_xlo);
    cudaGetSymbolAddress((void**)&yhi, g_yhi);   cudaGetSymbolAddress((void**)&ylo, g_ylo);
    cudaGetSymbolAddress((void**)&wallhi, g_wallhi);
    cudaGetSymbolAddress((void**)&walllo, g_walllo);
    cudaGetSymbolAddress((void**)&wohi, g_wohi); cudaGetSymbolAddress((void**)&wolo, g_wolo);

    const int smemG = NSTG * STAGE_B;   // 98304
    cudaFuncSetAttribute((const void*)hmma_gemm<true, false>,
                         cudaFuncAttributeMaxDynamicSharedMemorySize, smemG);
    cudaFuncSetAttribute((const void*)hmma_gemm<false, true>,
                         cudaFuncAttributeMaxDynamicSharedMemorySize, smemG);
    cudaFuncSetAttribute(attn_mma, cudaFuncAttributeMaxDynamicSharedMemorySize, ASMEM_TOTAL);

    // splits
    split_kernel<<<(MROWS * KDIM / 4 + 255) / 256, 256>>>(x_q, xhi, xlo, MROWS * KDIM);
    split_w3<<<dim3(NDIM * KDIM / 4 / 256, 3), 256>>>(w_q, w_k, w_v, wallhi, walllo);
    split_transpose<<<dim3(32, 32), dim3(32, 32)>>>(w_o, wohi, wolo);

    // fused QKV projection
    dim3 gridQKV(MROWS / 128, 24);
    hmma_gemm<true, false><<<gridQKV, 256, smemG>>>(xhi, xlo, wallhi, walllo,
                                                    nullptr, qkvhi, qkvlo);

    // attention (R11 structure, proven)
    dim3 gridA(TT / 128, BB * HH);
    attn_mma<<<gridA, 256, ASMEM_TOTAL>>>(qkvhi, qkvlo, yhi, ylo);

    // output projection (persistent)
    hmma_gemm<false, true><<<OPROJ_GRID, 256, smemG>>>(yhi, ylo, wohi, wolo,
                                                       out, nullptr, nullptr);
}

// round 17
// speedup vs baseline: 1.4251x; 1.4251x over previous
#include <cuda_runtime.h>
#include <cuda_fp16.h>
#include <cstdint>

// ---------------------------------------------------------------------------
// Problem: B=4, T=2048, C=1024, H=16, D=64.  out = attn(xWq, xWk, xWv) Wo
// R17: fp16 asymmetric 2-term split (activations exact hi+lo fp16 pair,
//      weights single-rounded fp16) -> 33% fewer HMMAs everywhere.
//      Pipeline structures = proven R14 shapes.
// ---------------------------------------------------------------------------
#define BB   4
#define TT   2048
#define CC   1024
#define HH   16
#define DD   64
#define MROWS (BB*TT)          // 8192
#define KDIM 1024
#define NDIM 1024
#define KOFF ((size_t)BB*HH*TT*DD)     // per-matrix q/k/v span

// ---- scratch ---------------------------------------------------------------
__device__ __half g_qkvhi[3*BB*HH*TT*DD];      // q,k,v (hi / single-rounded)
__device__ __half g_qlo[BB*HH*TT*DD];          // q residual (exact pair)
__device__ __half g_xhi[MROWS*KDIM], g_xlo[MROWS*KDIM];
__device__ __half g_yhi[MROWS*KDIM], g_ylo[MROWS*KDIM];
__device__ __half g_wall[3*NDIM*KDIM];         // wq,wk,wv single fp16
__device__ __half g_wo[NDIM*KDIM];             // wo^T single fp16

__device__ __forceinline__ uint32_t smem_u32(const void* p) {
    uint32_t a;
    asm("{ .reg .u64 t; cvta.to.shared.u64 t, %1; cvt.u32.u64 %0, t; }"
        : "=r"(a) : "l"(p));
    return a;
}
__device__ __forceinline__ void ldsm4(uint32_t& r0, uint32_t& r1,
                                      uint32_t& r2, uint32_t& r3, uint32_t addr) {
    asm volatile("ldmatrix.sync.aligned.m8n8.x4.shared.b16 {%0,%1,%2,%3}, [%4];"
                 : "=r"(r0), "=r"(r1), "=r"(r2), "=r"(r3) : "r"(addr));
}
__device__ __forceinline__ void ldsm4t(uint32_t& r0, uint32_t& r1,
                                       uint32_t& r2, uint32_t& r3, uint32_t addr) {
    asm volatile("ldmatrix.sync.aligned.m8n8.x4.trans.shared.b16 {%0,%1,%2,%3}, [%4];"
                 : "=r"(r0), "=r"(r1), "=r"(r2), "=r"(r3) : "r"(addr));
}
#define MMA_F16(d, a, b0, b1)                                               \
    asm volatile("mma.sync.aligned.m16n8k16.row.col.f32.f16.f16.f32 "       \
                 "{%0,%1,%2,%3}, {%4,%5,%6,%7}, {%8,%9}, {%0,%1,%2,%3};"    \
                 : "+f"((d)[0]), "+f"((d)[1]), "+f"((d)[2]), "+f"((d)[3])   \
                 : "r"((a)[0]), "r"((a)[1]), "r"((a)[2]), "r"((a)[3]),      \
                   "r"(b0), "r"(b1))
__device__ __forceinline__ void cpa16(uint32_t dst, const void* src) {
    asm volatile("cp.async.cg.shared.global [%0], [%1], 16;"
                 :: "r"(dst), "l"(src));
}
#define CP_COMMIT() asm volatile("cp.async.commit_group;")
#define CP_WAIT(n)  asm volatile("cp.async.wait_group %0;" :: "n"(n))
__device__ __forceinline__ float ex2f(float x) {
    float y; asm("ex2.approx.ftz.f32 %0, %1;" : "=f"(y) : "f"(x)); return y;
}
// fp16 exact-pair split: hi = rn16(v), lo = rn16(v - hi); packed pairs.
__device__ __forceinline__ void split2h(float a, float b, uint32_t& hi, uint32_t& lo) {
    __half2 h = __floats2half2_rn(a, b);
    float2 hf = __half22float2(h);
    __half2 l = __floats2half2_rn(a - hf.x, b - hf.y);
    hi = *(uint32_t*)&h;
    lo = *(uint32_t*)&l;
}

// ---------------------------------------------------------------------------
// split kernels
// ---------------------------------------------------------------------------
__global__ void split_x(const float* __restrict__ src,
                        __half* __restrict__ hi, __half* __restrict__ lo, int n)
{
    int i = (blockIdx.x * blockDim.x + threadIdx.x) * 4;
    if (i >= n) return;
    float4 v = *(const float4*)(src + i);
    uint32_t h0, l0, h1, l1;
    split2h(v.x, v.y, h0, l0);
    split2h(v.z, v.w, h1, l1);
    *(uint32_t*)(hi + i)     = h0; *(uint32_t*)(hi + i + 2) = h1;
    *(uint32_t*)(lo + i)     = l0; *(uint32_t*)(lo + i + 2) = l1;
}

// three weight matrices, single-rounded fp16
__global__ void cvt_w3(const float* __restrict__ w0, const float* __restrict__ w1,
                       const float* __restrict__ w2, __half* __restrict__ dst)
{
    const int mat = blockIdx.y;
    const float* src = (mat == 0) ? w0 : (mat == 1) ? w1 : w2;
    const size_t base = (size_t)mat * NDIM * KDIM;
    int i = (blockIdx.x * blockDim.x + threadIdx.x) * 4;
    float4 v = *(const float4*)(src + i);
    __half2 a = __floats2half2_rn(v.x, v.y);
    __half2 b = __floats2half2_rn(v.z, v.w);
    *(__half2*)(dst + base + i)     = a;
    *(__half2*)(dst + base + i + 2) = b;
}

// wo: [K,N] row-major -> [N,K] single fp16
__global__ void cvt_transpose(const float* __restrict__ W, __half* __restrict__ dst)
{
    __shared__ float tile[32][33];
    const int n0 = blockIdx.x * 32, k0 = blockIdx.y * 32;
    const int tx = threadIdx.x, ty = threadIdx.y;
    tile[ty][tx] = W[(k0 + ty) * NDIM + n0 + tx];
    __syncthreads();
    dst[(size_t)(n0 + ty) * KDIM + k0 + tx] = __float2half_rn(tile[tx][ty]);
}

// ---------------------------------------------------------------------------
// HMMA GEMM (fp16): A exact hi/lo pair, B single.  2 MMA passes per ksub.
// 3-stage swizzled cp.async ring (3 tiles/stage), 256 thr, 8 warps 32x64.
//   QKV=true  (PERSIST=false): grid (64, 24); fp16 split/scatter epilogue.
//   QKV=false (PERSIST=true) : grid 296, loops 512 tiles; fp32 epilogue.
// ---------------------------------------------------------------------------
#define TILE_B   (128 * 64)               // 8192 bytes per tile
#define STAGE_B  (3 * TILE_B)             // 24576
#define NSTG     3
#define OPROJ_GRID 296

template <bool QKV, bool PERSIST>
__global__ __launch_bounds__(256, 2)
void hmma_gemm(const __half* __restrict__ Ahi, const __half* __restrict__ Alo,
               const __half* __restrict__ BAll,
               float* __restrict__ C,
               __half* __restrict__ Chi, __half* __restrict__ Clo)
{
    extern __shared__ __align__(128) char sm[];
    const int tid  = threadIdx.x;
    const int wid  = tid >> 5;
    const int lane = tid & 31;

    const int wm0 = (wid & 3) * 32;
    const int wn0 = (wid >> 2) * 64;

    const int r0c = tid >> 2, c0c = tid & 3;
    const uint32_t smb = smem_u32(sm);
    const uint32_t s0 = r0c * 64 + ((c0c ^ ((r0c >> 1) & 3)) << 4);
    const uint32_t s1 = s0 + 64 * 64;

    const uint32_t aRow = wm0 + (lane & 15);
    const uint32_t aChunkBase = (lane >> 4);
    const uint32_t aXor = (aRow >> 1) & 3;
    const uint32_t g = lane >> 3;
    const uint32_t bRow = wn0 + (lane & 7) + ((g >> 1) << 3);
    const uint32_t bChunkBase = (g & 1);
    const uint32_t bXor = (bRow >> 1) & 3;

    const int NT   = PERSIST ? (64 * 8) : 1;
    const int step = PERSIST ? OPROJ_GRID : 1;

    for (int t = blockIdx.x; t < NT || !PERSIST; t += step) {
        int m0, n0, mat;
        if (PERSIST) {
            m0  = (t & 63) * 128;
            n0  = (t >> 6) * 128;
            mat = 0;
        } else {
            m0  = blockIdx.x * 128;
            mat = QKV ? (blockIdx.y >> 3) : 0;
            n0  = (QKV ? (blockIdx.y & 7) : blockIdx.y) * 128;
        }

        const __half* B = BAll + (size_t)mat * NDIM * KDIM;

        const size_t ga0 = (size_t)(m0 + r0c) * KDIM + c0c * 8;
        const size_t ga1 = (size_t)(m0 + r0c + 64) * KDIM + c0c * 8;
        const size_t gb0 = (size_t)(n0 + r0c) * KDIM + c0c * 8;
        const size_t gb1 = (size_t)(n0 + r0c + 64) * KDIM + c0c * 8;

        auto issue = [&](int st, int kt) {
            const int kc = kt * 32;
            const uint32_t bb = smb + st * STAGE_B;
            cpa16(bb + 0 * TILE_B + s0, Ahi + ga0 + kc);
            cpa16(bb + 0 * TILE_B + s1, Ahi + ga1 + kc);
            cpa16(bb + 1 * TILE_B + s0, Alo + ga0 + kc);
            cpa16(bb + 1 * TILE_B + s1, Alo + ga1 + kc);
            cpa16(bb + 2 * TILE_B + s0, B + gb0 + kc);
            cpa16(bb + 2 * TILE_B + s1, B + gb1 + kc);
            CP_COMMIT();
        };

        if (PERSIST) __syncthreads();
        issue(0, 0);
        issue(1, 1);

        float acc[2][8][4];
#pragma unroll
        for (int i = 0; i < 2; i++)
#pragma unroll
            for (int j = 0; j < 8; j++)
#pragma unroll
                for (int q = 0; q < 4; q++) acc[i][j][q] = 0.f;

        for (int kt = 0; kt < 32; kt++) {
            const int st = kt % NSTG;
            if (kt < 31) { CP_WAIT(1); } else { CP_WAIT(0); }
            __syncthreads();
            if (kt < 30) issue((kt + 2) % NSTG, kt + 2);

            const uint32_t base = smb + st * STAGE_B;
#pragma unroll
            for (int ksub = 0; ksub < 2; ksub++) {
                const uint32_t cA = (ksub * 2 + aChunkBase) ^ aXor;
                const uint32_t cB = (ksub * 2 + bChunkBase) ^ bXor;

                uint32_t ahi[2][4], alo[2][4];
#pragma unroll
                for (int mi = 0; mi < 2; mi++) {
                    const uint32_t off = (aRow + mi * 16) * 64 + (cA << 4);
                    ldsm4(ahi[mi][0], ahi[mi][1], ahi[mi][2], ahi[mi][3],
                          base + 0 * TILE_B + off);
                    ldsm4(alo[mi][0], alo[mi][1], alo[mi][2], alo[mi][3],
                          base + 1 * TILE_B + off);
                }
                uint32_t bh[4][4];
#pragma unroll
                for (int pj = 0; pj < 4; pj++) {
                    const uint32_t off = (bRow + pj * 16) * 64 + (cB << 4);
                    ldsm4(bh[pj][0], bh[pj][1], bh[pj][2], bh[pj][3],
                          base + 2 * TILE_B + off);
                }

                // pass 1: ahi * b   (16 MMAs, distinct targets)
#pragma unroll
                for (int pj = 0; pj < 4; pj++)
#pragma unroll
                    for (int mi = 0; mi < 2; mi++) {
                        MMA_F16(acc[mi][2*pj],   ahi[mi], bh[pj][0], bh[pj][1]);
                        MMA_F16(acc[mi][2*pj+1], ahi[mi], bh[pj][2], bh[pj][3]);
                    }
                // pass 2: alo * b   (16 MMAs)
#pragma unroll
                for (int pj = 0; pj < 4; pj++)
#pragma unroll
                    for (int mi = 0; mi < 2; mi++) {
                        MMA_F16(acc[mi][2*pj],   alo[mi], bh[pj][0], bh[pj][1]);
                        MMA_F16(acc[mi][2*pj+1], alo[mi], bh[pj][2], bh[pj][3]);
                    }
            }
        }

        // ---- epilogue -----------------------------------------------------
        const float preScale = (QKV && mat == 0) ? (0.125f * 1.44269504088896341f) : 1.0f;
#pragma unroll
        for (int mi = 0; mi < 2; mi++) {
#pragma unroll
            for (int nt = 0; nt < 8; nt++) {
                const int mrow0 = m0 + wm0 + mi * 16 + (lane >> 2);
                const int ncol  = n0 + wn0 + nt * 8 + (lane & 3) * 2;
                if (QKV) {
                    const int h = ncol >> 6, d = ncol & 63;
#pragma unroll
                    for (int half = 0; half < 2; half++) {
                        const int m = mrow0 + half * 8;
                        const int b = m >> 11, tt2 = m & 2047;
                        const size_t off = (size_t)mat * KOFF
                                         + (((size_t)(b * HH + h) * TT + tt2) * DD + d);
                        uint32_t hh, ll;
                        split2h(acc[mi][nt][half * 2] * preScale,
                                acc[mi][nt][half * 2 + 1] * preScale, hh, ll);
                        *(uint32_t*)(Chi + off) = hh;
                        if (mat == 0)                       // residual only for Q
                            *(uint32_t*)(Clo + off) = ll;
                    }
                } else {
#pragma unroll
                    for (int half = 0; half < 2; half++) {
                        float* o = C + (size_t)(mrow0 + half * 8) * NDIM + ncol;
                        *(float2*)o = make_float2(acc[mi][nt][half * 2],
                                                  acc[mi][nt][half * 2 + 1]);
                    }
                }
            }
        }
        if (!PERSIST) break;
    }
}

// ---------------------------------------------------------------------------
// HMMA flash attention (fp16 2-term). CTA = 128 q-rows, 8 warps, block 256.
// Q exact hi/lo pair (staged via ring stages 0-1, then recycled); K,V single
// fp16 -> 2 tiles/stage, 3-stage cp.async ring. P exact fp16 pair in regs.
// grid = (16 qtiles [reversed], 64 bh). 2 CTAs/SM.
// ---------------------------------------------------------------------------
#define ASTRB    144
#define ATILE_B  (64 * ASTRB)              // 9216
#define ASTAGE_B (2 * ATILE_B)             // 18432 (K, V)
#define ASMEM_TOTAL (3 * ASTAGE_B)         // 55296

__global__ __launch_bounds__(256, 2)
void attn_mma(const __half* __restrict__ QKVhi, const __half* __restrict__ Qlo,
              __half* __restrict__ Yhi, __half* __restrict__ Ylo)
{
    extern __shared__ __align__(128) char smA[];
    const int tid  = threadIdx.x;
    const int wid  = tid >> 5;
    const int lane = tid & 31;
    const int qt   = (int)(gridDim.x - 1) - (int)blockIdx.x;
    const int bh   = blockIdx.y;
    const int b    = bh >> 4;
    const int h    = bh & 15;
    const int q0   = qt * 128;

    const size_t bho = (size_t)bh * TT * DD;
    const __half* qh = QKVhi + bho;
    const __half* ql = Qlo + bho;
    const __half* kh = QKVhi + KOFF + bho;
    const __half* vh = QKVhi + 2 * KOFF + bho;

    const uint32_t smb = smem_u32(smA);

    auto issue_stage = [&](int buf, int ktile) {
        const uint32_t sb = smb + buf * ASTAGE_B;
        const int k0 = ktile * 64;
#pragma unroll
        for (int i = 0; i < 2; i++) {
            const int c = tid + i * 256;
            const int r = c >> 3, col = c & 7;
            const uint32_t doff = r * ASTRB + col * 16;
            const size_t goff = (size_t)(k0 + r) * DD + col * 8;
            cpa16(sb + 0 * ATILE_B + doff, kh + goff);
            cpa16(sb + 1 * ATILE_B + doff, vh + goff);
        }
        CP_COMMIT();
    };

    // ---- stage Q: hi -> ring stage 0 (2 slots), lo -> ring stage 1 --------
    {
#pragma unroll
        for (int i = 0; i < 4; i++) {
            const int c = tid + i * 256;           // 0..1023
            const int r = c >> 3, col = c & 7;     // r 0..127
            const uint32_t doff = (r >> 6) * ATILE_B + (r & 63) * ASTRB + col * 16;
            const size_t goff = (size_t)(q0 + r) * DD + col * 8;
            cpa16(smb + doff, qh + goff);
            cpa16(smb + ASTAGE_B + doff, ql + goff);
        }
        CP_COMMIT();
    }
    CP_WAIT(0);
    __syncthreads();

    // ---- persistent Q fragments (hi + lo) ---------------------------------
    const int l7  = lane & 7;
    const int l8  = (lane >> 3) & 1;
    const int l16 = lane >> 4;
    uint32_t qfh[4][4], qfl[4][4];
    {
        const uint32_t qrow = wid * 16 + l7 + l8 * 8;
        const uint32_t qbase = (qrow >> 6) * ATILE_B + (qrow & 63) * ASTRB;
#pragma unroll
        for (int kc = 0; kc < 4; kc++) {
            const uint32_t off = qbase + kc * 32 + l16 * 16;
            ldsm4(qfh[kc][0], qfh[kc][1], qfh[kc][2], qfh[kc][3], smb + off);
            ldsm4(qfl[kc][0], qfl[kc][1], qfl[kc][2], qfl[kc][3],
                  smb + ASTAGE_B + off);
        }
    }
    __syncthreads();          // Q reads done; ring stages 0-1 reusable

    issue_stage(0, 0);
    issue_stage(1, 1);

    float accO[8][4];
    float mrow[2], lrow[2];
#pragma unroll
    for (int nt = 0; nt < 8; nt++)
#pragma unroll
        for (int q = 0; q < 4; q++) accO[nt][q] = 0.f;
    mrow[0] = mrow[1] = -1e30f;
    lrow[0] = lrow[1] = 0.f;

    const int rowg0 = q0 + wid * 16 + (lane >> 2);
    const int colg0 = (lane & 3) * 2;
    const int nk = 2 * (qt + 1);

    for (int kt = 0; kt < nk; kt++) {
        const int st = kt % 3;
        if (kt < nk - 1) { CP_WAIT(1); } else { CP_WAIT(0); }
        __syncthreads();
        if (kt + 2 < nk) issue_stage((kt + 2) % 3, kt + 2);

        const uint32_t base = smb + st * ASTAGE_B;
        const uint32_t krow = l7 + l8 * 8;

        // ---- S = Q K^T (2-term: qhi*k + qlo*k) ----------------------------
        float S[8][4];
#pragma unroll
        for (int nt = 0; nt < 8; nt++)
#pragma unroll
            for (int q = 0; q < 4; q++) S[nt][q] = 0.f;

#pragma unroll
        for (int kc = 0; kc < 4; kc++) {
#pragma unroll
            for (int p = 0; p < 4; p++) {
                const uint32_t off = (p * 16 + krow) * ASTRB + kc * 32 + l16 * 16;
                uint32_t b4[4];
                ldsm4(b4[0], b4[1], b4[2], b4[3], base + 0 * ATILE_B + off);
                MMA_F16(S[2*p],   qfh[kc], b4[0], b4[2]);
                MMA_F16(S[2*p],   qfl[kc], b4[0], b4[2]);
                MMA_F16(S[2*p+1], qfh[kc], b4[1], b4[3]);
                MMA_F16(S[2*p+1], qfl[kc], b4[1], b4[3]);
            }
        }

        // ---- causal mask --------------------------------------------------
        const int k0g = kt * 64;
        if (k0g + 63 > q0 + wid * 16) {
#pragma unroll
            for (int nt = 0; nt < 8; nt++) {
                const int cg = k0g + nt * 8 + colg0;
#pragma unroll
                for (int i = 0; i < 2; i++) {
                    const int rg = rowg0 + i * 8;
                    if (cg     > rg) S[nt][2*i]     = -1e30f;
                    if (cg + 1 > rg) S[nt][2*i + 1] = -1e30f;
                }
            }
        }

        // ---- online softmax (log2 units; scale folded into Q) -------------
#pragma unroll
        for (int i = 0; i < 2; i++) {
            float mx = -1e30f;
#pragma unroll
            for (int nt = 0; nt < 8; nt++)
                mx = fmaxf(mx, fmaxf(S[nt][2*i], S[nt][2*i+1]));
            mx = fmaxf(mx, __shfl_xor_sync(0xffffffffu, mx, 1));
            mx = fmaxf(mx, __shfl_xor_sync(0xffffffffu, mx, 2));
            const float mn = fmaxf(mrow[i], mx);
            const float fac = ex2f(mrow[i] - mn);
            float rs = 0.f;
#pragma unroll
            for (int nt = 0; nt < 8; nt++) {
                float p0 = ex2f(S[nt][2*i]   - mn);
                float p1 = ex2f(S[nt][2*i+1] - mn);
                S[nt][2*i] = p0; S[nt][2*i+1] = p1;
                rs += p0 + p1;
            }
            rs += __shfl_xor_sync(0xffffffffu, rs, 1);
            rs += __shfl_xor_sync(0xffffffffu, rs, 2);
            lrow[i] = lrow[i] * fac + rs;
            mrow[i] = mn;
#pragma unroll
            for (int nt = 0; nt < 8; nt++) {
                accO[nt][2*i]   *= fac;
                accO[nt][2*i+1] *= fac;
            }
        }

        // ---- O += P V (2-term: Phi*v + Plo*v; P exact fp16 pair) ----------
#pragma unroll
        for (int kc = 0; kc < 4; kc++) {
            uint32_t pah[4], pal[4];
            split2h(S[2*kc][0],   S[2*kc][1],   pah[0], pal[0]);
            split2h(S[2*kc][2],   S[2*kc][3],   pah[1], pal[1]);
            split2h(S[2*kc+1][0], S[2*kc+1][1], pah[2], pal[2]);
            split2h(S[2*kc+1][2], S[2*kc+1][3], pah[3], pal[3]);
#pragma unroll
            for (int p = 0; p < 4; p++) {
                const uint32_t off = (kc * 16 + krow) * ASTRB + p * 32 + l16 * 16;
                uint32_t v4[4];
                ldsm4t(v4[0], v4[1], v4[2], v4[3], base + 1 * ATILE_B + off);
                MMA_F16(accO[2*p],   pah, v4[0], v4[1]);
                MMA_F16(accO[2*p],   pal, v4[0], v4[1]);
                MMA_F16(accO[2*p+1], pah, v4[2], v4[3]);
                MMA_F16(accO[2*p+1], pal, v4[2], v4[3]);
            }
        }
    }

    // ---- epilogue: y[b,t,h*64+d] exact fp16 pair --------------------------
    const float inv0 = 1.0f / lrow[0];
    const float inv1 = 1.0f / lrow[1];
#pragma unroll
    for (int i = 0; i < 2; i++) {
        const float inv = i ? inv1 : inv0;
#pragma unroll
        for (int nt = 0; nt < 8; nt++) {
            const int d = nt * 8 + colg0;
            const size_t off = ((size_t)(b * TT + (rowg0 + i * 8))) * CC + h * DD + d;
            uint32_t hh, ll;
            split2h(accO[nt][2*i] * inv, accO[nt][2*i+1] * inv, hh, ll);
            *(uint32_t*)(Yhi + off) = hh;
            *(uint32_t*)(Ylo + off) = ll;
        }
    }
}

// ---------------------------------------------------------------------------
// launch
// ---------------------------------------------------------------------------
extern "C" void kernel_launch(void* const* d_in, const int* in_sizes, int n_in,
                              void* d_out, int out_size)
{
    const float* x_q = (const float*)d_in[0];
    const float* w_q = (const float*)d_in[1];
    const float* w_k = (const float*)d_in[2];
    const float* w_v = (const float*)d_in[3];
    const float* w_o = (const float*)d_in[4];
    float* out = (float*)d_out;

    __half *qkvhi, *qlo, *xhi, *xlo, *yhi, *ylo, *wall, *wo;
    cudaGetSymbolAddress((void**)&qkvhi, g_qkvhi);
    cudaGetSymbolAddress((void**)&qlo,   g_qlo);
    cudaGetSymbolAddress((void**)&xhi, g_xhi);   cudaGetSymbolAddress((void**)&xlo, g_xlo);
    cudaGetSymbolAddress((void**)&yhi, g_yhi);   cudaGetSymbolAddress((void**)&ylo, g_ylo);
    cudaGetSymbolAddress((void**)&wall, g_wall);
    cudaGetSymbolAddress((void**)&wo,   g_wo);

    const int smemG = NSTG * STAGE_B;   // 73728
    cudaFuncSetAttribute((const void*)hmma_gemm<true, false>,
                         cudaFuncAttributeMaxDynamicSharedMemorySize, smemG);
    cudaFuncSetAttribute((const void*)hmma_gemm<false, true>,
                         cudaFuncAttributeMaxDynamicSharedMemorySize, smemG);
    cudaFuncSetAttribute(attn_mma, cudaFuncAttributeMaxDynamicSharedMemorySize, ASMEM_TOTAL);

    // splits / conversions
    split_x<<<(MROWS * KDIM / 4 + 255) / 256, 256>>>(x_q, xhi, xlo, MROWS * KDIM);
    cvt_w3<<<dim3(NDIM * KDIM / 4 / 256, 3), 256>>>(w_q, w_k, w_v, wall);
    cvt_transpose<<<dim3(32, 32), dim3(32, 32)>>>(w_o, wo);

    // fused QKV projection
    dim3 gridQKV(MROWS / 128, 24);
    hmma_gemm<true, false><<<gridQKV, 256, smemG>>>(xhi, xlo, wall,
                                                    nullptr, qkvhi, qlo);

    // attention
    dim3 gridA(TT / 128, BB * HH);
    attn_mma<<<gridA, 256, ASMEM_TOTAL>>>(qkvhi, qlo, yhi, ylo);

    // output projection (persistent)
    hmma_gemm<false, true><<<OPROJ_GRID, 256, smemG>>>(yhi, ylo, wo,
                                                       out, nullptr, nullptr);
}